// round 16
// baseline (speedup 1.0000x reference)
#include <cuda_runtime.h>
#include <stdint.h>

// VolGeoNet trilinear interp: cell-resolved counting sort, work item =
// (channel-half, 4^3 region) with work stealing, per-cell corner-row reuse.
// R13 main kernel (best measured) + inline block-prefix (no fixup pass).
// Inputs: x [B,3] f32, grid_value [65^3,1] f32, grid_feature [65^3,256] f32.
// Output: concat(out [B,1], feat [B,256]) float, out first.

#define N1 65
#define W_FEAT 256
#define MAXB 262144
#define NREGIONS 4096             // 16^3 regions of 4^3 cells
#define NKEYS (NREGIONS * 64)     // 262144 cells, region-major
#define SCAN_BLOCKS 256           // NKEYS / 1024
#define NITEMS (2 * NREGIONS)
#define GRID_MAIN 1480            // 10 CTAs/SM

__device__ int    g_hist[NKEYS];          // zero at entry every call (scan1 resets)
__device__ int    g_binstart[NKEYS + 1];  // block-local exclusive prefix
__device__ int    g_bsum[SCAN_BLOCKS];
__device__ int    g_bsumx[SCAN_BLOCKS + 1];
__device__ int    g_keyarr[MAXB];
__device__ int    g_rank[MAXB];
__device__ float4 g_xs[MAXB];             // sorted (x,y,z, bitcast point-index)
__device__ int    g_item;                 // work-stealing cursor (reset by histo)

__device__ __forceinline__ int cell_key(int ix, int iy, int iz)
{
    const int region = ((ix >> 2) << 8) | ((iy >> 2) << 4) | (iz >> 2);
    const int cig    = ((ix & 3) << 4) | ((iy & 3) << 2) | (iz & 3);
    return (region << 6) | cig;
}

__global__ void histo_kernel(const float* __restrict__ x, int B)
{
    int p = blockIdx.x * blockDim.x + threadIdx.x;
    if (p == 0) g_item = 0;
    if (p >= B) return;
    const float rx = (x[p * 3 + 0] + 1.0f) * 32.0f;
    const float ry = (x[p * 3 + 1] + 1.0f) * 32.0f;
    const float rz = (x[p * 3 + 2] + 1.0f) * 32.0f;
    int ix = (int)floorf(rx); ix = ix < 0 ? 0 : (ix > 63 ? 63 : ix);
    int iy = (int)floorf(ry); iy = iy < 0 ? 0 : (iy > 63 ? 63 : iy);
    int iz = (int)floorf(rz); iz = iz < 0 ? 0 : (iz > 63 ? 63 : iz);
    const int key = cell_key(ix, iy, iz);
    g_keyarr[p] = key;
    g_rank[p] = atomicAdd(&g_hist[key], 1);
}

// Block-local exclusive scan over 1024 bins; emits block totals; resets g_hist.
__global__ void __launch_bounds__(1024) scan1_kernel()
{
    __shared__ int s[1024];
    const int t = threadIdx.x;
    const int idx = blockIdx.x * 1024 + t;
    const int v = g_hist[idx];
    s[t] = v;
    __syncthreads();
    for (int off = 1; off < 1024; off <<= 1) {
        int a = 0;
        if (t >= off) a = s[t - off];
        __syncthreads();
        if (t >= off) s[t] += a;
        __syncthreads();
    }
    g_binstart[idx] = s[t] - v;               // block-local exclusive
    if (t == 1023) g_bsum[blockIdx.x] = s[t];
    g_hist[idx] = 0;
}

// Exclusive-scan the 256 block totals; seed sentinels so
// gbin(NKEYS) = B without a fixup pass.
__global__ void __launch_bounds__(SCAN_BLOCKS) scan2_kernel(int B)
{
    __shared__ int s[SCAN_BLOCKS];
    const int t = threadIdx.x;
    const int v = g_bsum[t];
    s[t] = v;
    __syncthreads();
    for (int off = 1; off < SCAN_BLOCKS; off <<= 1) {
        int a = 0;
        if (t >= off) a = s[t - off];
        __syncthreads();
        if (t >= off) s[t] += a;
        __syncthreads();
    }
    g_bsumx[t] = s[t] - v;
    if (t == 0) {
        g_bsumx[SCAN_BLOCKS] = 0;
        g_binstart[NKEYS] = B;
    }
}

__global__ void scatter_kernel(const float* __restrict__ x, int B)
{
    int p = blockIdx.x * blockDim.x + threadIdx.x;
    if (p >= B) return;
    const int key = g_keyarr[p];
    const int dst = g_binstart[key] + g_bsumx[key >> 10] + g_rank[p];
    g_xs[dst] = make_float4(x[p * 3 + 0], x[p * 3 + 1], x[p * 3 + 2],
                            __int_as_float(p));
}

// ──────────────────────────────────────────────────────────────────────────
// Main kernel: work item = (half, region). 4 warps of the CTA stride over the
// region's 64 cells; per non-empty cell the 8 corner rows (and gv corner) are
// loaded once and reused for every point in the cell. All per-iteration loads
// are independent (MLP ~10) — latency already hidden; no staging/barriers.
__global__ void __launch_bounds__(128, 10) trilerp_main_kernel(
    const float* __restrict__ gv,
    const float* __restrict__ gf,
    float* __restrict__ out_val,   // [B]
    float* __restrict__ out_feat)  // [B, 256]
{
    __shared__ int s_item;
    const int tid  = threadIdx.x;
    const int wid  = tid >> 5;
    const int lane = tid & 31;

    for (;;) {
        if (tid == 0) s_item = atomicAdd(&g_item, 1);
        __syncthreads();
        const int item = s_item;
        __syncthreads();
        if (item >= NITEMS) return;

        const int half   = item >> 12;
        const int region = item & (NREGIONS - 1);
        const int rx0 = ((region >> 8) & 15) << 2;
        const int ry0 = ((region >> 4) & 15) << 2;
        const int rz0 = (region & 15) << 2;

        const int coff = (half << 5) + lane;   // float4 column within 1KB row
        const int keybase = region << 6;
        const int bprefix = g_bsumx[keybase >> 10];   // uniform for the region

        for (int cig = wid; cig < 64; cig += 4) {
            const int cstart = g_binstart[keybase + cig] +
                               ((keybase + cig) >> 10 == keybase >> 10
                                    ? bprefix : g_bsumx[(keybase + cig) >> 10]);
            const int knext = keybase + cig + 1;
            const int cend = g_binstart[knext] +
                             (knext >> 10 == keybase >> 10 ? bprefix
                                                          : g_bsumx[knext >> 10]);
            if (cstart == cend) continue;

            const int ix = rx0 + (cig >> 4);
            const int iy = ry0 + ((cig >> 2) & 3);
            const int iz = rz0 + (cig & 3);
            const int base = (ix * N1 + iy) * N1 + iz;

            // Load 8 corner rows once for this cell.
            const float4* r = (const float4*)gf + (size_t)base * (W_FEAT / 4) + coff;
            const float4 f0 = __ldg(r);
            const float4 f1 = __ldg(r + (W_FEAT / 4));
            const float4 f2 = __ldg(r + N1 * (W_FEAT / 4));
            const float4 f3 = __ldg(r + (N1 + 1) * (W_FEAT / 4));
            const float4* rh = r + N1 * N1 * (W_FEAT / 4);
            const float4 f4 = __ldg(rh);
            const float4 f5 = __ldg(rh + (W_FEAT / 4));
            const float4 f6 = __ldg(rh + N1 * (W_FEAT / 4));
            const float4 f7 = __ldg(rh + (N1 + 1) * (W_FEAT / 4));

            // gv corner value for lanes 0..7 (used by half 0 only).
            float gvrow = 0.0f;
            if (half == 0 && lane < 8) {
                const int off = ((lane & 4) ? N1 * N1 : 0) +
                                ((lane & 2) ? N1 : 0) + (lane & 1);
                gvrow = __ldg(gv + base + off);
            }

            for (int j = cstart; j < cend; j++) {
                const float4 xp = __ldcs(&g_xs[j]);
                const int p = __float_as_int(xp.w);

                const float rx = (xp.x + 1.0f) * 32.0f;
                const float ry = (xp.y + 1.0f) * 32.0f;
                const float rz = (xp.z + 1.0f) * 32.0f;

                const bool valid = (rx >= 0.0f) && (rx <= 64.0f) &&
                                   (ry >= 0.0f) && (ry <= 64.0f) &&
                                   (rz >= 0.0f) && (rz <= 64.0f);
                const float vmask = valid ? 1.0f : 0.0f;

                const float tx = rx - (float)ix;
                const float ty = ry - (float)iy;
                const float tz = rz - (float)iz;
                const float wx0 = 1.0f - tx, wy0 = 1.0f - ty, wz0 = 1.0f - tz;

                const float w0 = wx0 * wy0 * wz0;
                const float w1 = wx0 * wy0 * tz;
                const float w2 = wx0 * ty  * wz0;
                const float w3 = wx0 * ty  * tz;
                const float w4 = tx  * wy0 * wz0;
                const float w5 = tx  * wy0 * tz;
                const float w6 = tx  * ty  * wz0;
                const float w7 = tx  * ty  * tz;

                float s0, s1, s2, s3;
                s0 = w0 * f0.x; s1 = w0 * f0.y; s2 = w0 * f0.z; s3 = w0 * f0.w;
                s0 = fmaf(w1, f1.x, s0); s1 = fmaf(w1, f1.y, s1);
                s2 = fmaf(w1, f1.z, s2); s3 = fmaf(w1, f1.w, s3);
                s0 = fmaf(w2, f2.x, s0); s1 = fmaf(w2, f2.y, s1);
                s2 = fmaf(w2, f2.z, s2); s3 = fmaf(w2, f2.w, s3);
                s0 = fmaf(w3, f3.x, s0); s1 = fmaf(w3, f3.y, s1);
                s2 = fmaf(w3, f3.z, s2); s3 = fmaf(w3, f3.w, s3);
                s0 = fmaf(w4, f4.x, s0); s1 = fmaf(w4, f4.y, s1);
                s2 = fmaf(w4, f4.z, s2); s3 = fmaf(w4, f4.w, s3);
                s0 = fmaf(w5, f5.x, s0); s1 = fmaf(w5, f5.y, s1);
                s2 = fmaf(w5, f5.z, s2); s3 = fmaf(w5, f5.w, s3);
                s0 = fmaf(w6, f6.x, s0); s1 = fmaf(w6, f6.y, s1);
                s2 = fmaf(w6, f6.z, s2); s3 = fmaf(w6, f6.w, s3);
                s0 = fmaf(w7, f7.x, s0); s1 = fmaf(w7, f7.y, s1);
                s2 = fmaf(w7, f7.z, s2); s3 = fmaf(w7, f7.w, s3);

                float4* frow = (float4*)(out_feat + (size_t)p * W_FEAT);
                __stcs(frow + coff,
                       make_float4(s0 * vmask, s1 * vmask, s2 * vmask, s3 * vmask));

                if (half == 0) {
                    const float wxs = (lane & 4) ? tx : wx0;
                    const float wys = (lane & 2) ? ty : wy0;
                    const float wzs = (lane & 1) ? tz : wz0;
                    float gvv = (lane < 8) ? wxs * wys * wzs * gvrow : 0.0f;
                    gvv += __shfl_xor_sync(0xffffffffu, gvv, 4);
                    gvv += __shfl_xor_sync(0xffffffffu, gvv, 2);
                    gvv += __shfl_xor_sync(0xffffffffu, gvv, 1);
                    if (lane == 0) out_val[p] = gvv * vmask;
                }
            }
        }
    }
}

// Fallback (B > MAXB): direct global-gather version, unsorted.
__global__ void __launch_bounds__(256) trilerp_kernel(
    const float* __restrict__ x,
    const float* __restrict__ gv,
    const float* __restrict__ gf,
    float* __restrict__ out_val,
    float* __restrict__ out_feat,
    int B)
{
    const int p = (blockIdx.x * blockDim.x + threadIdx.x) >> 5;
    const int lane = threadIdx.x & 31;
    if (p >= B) return;

    const float rx = (__ldg(x + p * 3 + 0) + 1.0f) * 32.0f;
    const float ry = (__ldg(x + p * 3 + 1) + 1.0f) * 32.0f;
    const float rz = (__ldg(x + p * 3 + 2) + 1.0f) * 32.0f;
    const bool valid = (rx >= 0.0f) && (rx <= 64.0f) && (ry >= 0.0f) &&
                       (ry <= 64.0f) && (rz >= 0.0f) && (rz <= 64.0f);
    const float vmask = valid ? 1.0f : 0.0f;
    int ix = (int)floorf(rx); ix = ix < 0 ? 0 : (ix > 63 ? 63 : ix);
    int iy = (int)floorf(ry); iy = iy < 0 ? 0 : (iy > 63 ? 63 : iy);
    int iz = (int)floorf(rz); iz = iz < 0 ? 0 : (iz > 63 ? 63 : iz);
    const float tx = rx - ix, ty = ry - iy, tz = rz - iz;
    const int base = (ix * N1 + iy) * N1 + iz;
    const float wx0 = 1.0f - tx, wy0 = 1.0f - ty, wz0 = 1.0f - tz;
    float w[8] = { wx0*wy0*wz0, wx0*wy0*tz, wx0*ty*wz0, wx0*ty*tz,
                   tx*wy0*wz0,  tx*wy0*tz,  tx*ty*wz0,  tx*ty*tz };
    const int offs[8] = { 0, 1, N1, N1+1, N1*N1, N1*N1+1, N1*N1+N1, N1*N1+N1+1 };

    float gvv = 0.0f;
    if (lane < 8) gvv = w[lane] * __ldg(gv + base + offs[lane]);
    gvv += __shfl_xor_sync(0xffffffffu, gvv, 4);
    gvv += __shfl_xor_sync(0xffffffffu, gvv, 2);
    gvv += __shfl_xor_sync(0xffffffffu, gvv, 1);
    if (lane == 0) out_val[p] = gvv * vmask;

    float a0=0,a1=0,a2=0,a3=0,b0=0,b1=0,b2=0,b3=0;
#pragma unroll
    for (int c = 0; c < 8; c++) {
        const float4* row = (const float4*)(gf + (size_t)(base + offs[c]) * W_FEAT);
        const float4 fa = __ldg(row + lane);
        const float4 fb = __ldg(row + lane + 32);
        const float wc = w[c];
        a0 = fmaf(wc, fa.x, a0); a1 = fmaf(wc, fa.y, a1);
        a2 = fmaf(wc, fa.z, a2); a3 = fmaf(wc, fa.w, a3);
        b0 = fmaf(wc, fb.x, b0); b1 = fmaf(wc, fb.y, b1);
        b2 = fmaf(wc, fb.z, b2); b3 = fmaf(wc, fb.w, b3);
    }
    float4* frow = (float4*)(out_feat + (size_t)p * W_FEAT);
    frow[lane]      = make_float4(a0*vmask, a1*vmask, a2*vmask, a3*vmask);
    frow[lane + 32] = make_float4(b0*vmask, b1*vmask, b2*vmask, b3*vmask);
}

extern "C" void kernel_launch(void* const* d_in, const int* in_sizes, int n_in,
                              void* d_out, int out_size)
{
    const float* x  = (const float*)d_in[0];
    const float* gv = (const float*)d_in[1];
    const float* gf = (const float*)d_in[2];
    float* out = (float*)d_out;

    const int B = in_sizes[0] / 3;
    float* out_val  = out;        // [B]
    float* out_feat = out + B;    // [B, 256]

    if (B <= MAXB) {
        histo_kernel<<<(B + 255) / 256, 256>>>(x, B);
        scan1_kernel<<<SCAN_BLOCKS, 1024>>>();
        scan2_kernel<<<1, SCAN_BLOCKS>>>(B);
        scatter_kernel<<<(B + 255) / 256, 256>>>(x, B);
        trilerp_main_kernel<<<GRID_MAIN, 128>>>(gv, gf, out_val, out_feat);
    } else {
        const int blocks = (B + 7) / 8;
        trilerp_kernel<<<blocks, 256>>>(x, gv, gf, out_val, out_feat, B);
    }
}

// round 17
// speedup vs baseline: 1.4740x; 1.4740x over previous
#include <cuda_runtime.h>
#include <stdint.h>

// VolGeoNet trilinear interp: cell-resolved counting sort, work item =
// (channel-half, 4^3 region) with work stealing. Warps own (x,y) z-columns
// of 4 cells and slide the shared z-plane (4 corner rows) between adjacent
// cells -> ~24% fewer gather loads vs per-cell reload. R13-verified chain
// (separate fixup pass, __ldg point loads).
// Inputs: x [B,3] f32, grid_value [65^3,1] f32, grid_feature [65^3,256] f32.
// Output: concat(out [B,1], feat [B,256]) float, out first.

#define N1 65
#define W_FEAT 256
#define MAXB 262144
#define NREGIONS 4096             // 16^3 regions of 4^3 cells
#define NKEYS (NREGIONS * 64)     // 262144 cells, region-major, z fastest
#define SCAN_BLOCKS 256           // NKEYS / 1024
#define NITEMS (2 * NREGIONS)
#define GRID_MAIN 1480            // 10 CTAs/SM

__device__ int    g_hist[NKEYS];          // zero at entry every call (scan1 resets)
__device__ int    g_binstart[NKEYS + 1];
__device__ int    g_bsum[SCAN_BLOCKS];
__device__ int    g_bsumx[SCAN_BLOCKS];
__device__ int    g_keyarr[MAXB];
__device__ int    g_rank[MAXB];
__device__ float4 g_xs[MAXB];             // sorted (x,y,z, bitcast point-index)
__device__ int    g_item;                 // work-stealing cursor (reset by histo)

__device__ __forceinline__ int cell_key(int ix, int iy, int iz)
{
    const int region = ((ix >> 2) << 8) | ((iy >> 2) << 4) | (iz >> 2);
    const int cig    = ((ix & 3) << 4) | ((iy & 3) << 2) | (iz & 3);
    return (region << 6) | cig;
}

__global__ void histo_kernel(const float* __restrict__ x, int B)
{
    int p = blockIdx.x * blockDim.x + threadIdx.x;
    if (p == 0) g_item = 0;
    if (p >= B) return;
    const float rx = (x[p * 3 + 0] + 1.0f) * 32.0f;
    const float ry = (x[p * 3 + 1] + 1.0f) * 32.0f;
    const float rz = (x[p * 3 + 2] + 1.0f) * 32.0f;
    int ix = (int)floorf(rx); ix = ix < 0 ? 0 : (ix > 63 ? 63 : ix);
    int iy = (int)floorf(ry); iy = iy < 0 ? 0 : (iy > 63 ? 63 : iy);
    int iz = (int)floorf(rz); iz = iz < 0 ? 0 : (iz > 63 ? 63 : iz);
    const int key = cell_key(ix, iy, iz);
    g_keyarr[p] = key;
    g_rank[p] = atomicAdd(&g_hist[key], 1);
}

// Block-local exclusive scan over 1024 bins; emits block totals; resets g_hist.
__global__ void __launch_bounds__(1024) scan1_kernel()
{
    __shared__ int s[1024];
    const int t = threadIdx.x;
    const int idx = blockIdx.x * 1024 + t;
    const int v = g_hist[idx];
    s[t] = v;
    __syncthreads();
    for (int off = 1; off < 1024; off <<= 1) {
        int a = 0;
        if (t >= off) a = s[t - off];
        __syncthreads();
        if (t >= off) s[t] += a;
        __syncthreads();
    }
    g_binstart[idx] = s[t] - v;               // block-local exclusive
    if (t == 1023) g_bsum[blockIdx.x] = s[t];
    g_hist[idx] = 0;
}

// Exclusive-scan the 256 block totals.
__global__ void __launch_bounds__(SCAN_BLOCKS) scan2_kernel(int B)
{
    __shared__ int s[SCAN_BLOCKS];
    const int t = threadIdx.x;
    const int v = g_bsum[t];
    s[t] = v;
    __syncthreads();
    for (int off = 1; off < SCAN_BLOCKS; off <<= 1) {
        int a = 0;
        if (t >= off) a = s[t - off];
        __syncthreads();
        if (t >= off) s[t] += a;
        __syncthreads();
    }
    g_bsumx[t] = s[t] - v;
    if (t == SCAN_BLOCKS - 1) g_binstart[NKEYS] = B;
}

// Globalize binstart (add block prefix).
__global__ void __launch_bounds__(1024) fixup_kernel()
{
    const int idx = blockIdx.x * 1024 + threadIdx.x;
    g_binstart[idx] += g_bsumx[idx >> 10];
}

__global__ void scatter_kernel(const float* __restrict__ x, int B)
{
    int p = blockIdx.x * blockDim.x + threadIdx.x;
    if (p >= B) return;
    const int key = g_keyarr[p];
    const int dst = g_binstart[key] + g_rank[p];
    g_xs[dst] = make_float4(x[p * 3 + 0], x[p * 3 + 1], x[p * 3 + 2],
                            __int_as_float(p));
}

// ──────────────────────────────────────────────────────────────────────────
// Main kernel: work item = (half, region). Each warp takes (x,y) columns
// (16 per region, stride 4); within a column it walks 4 z-cells, sliding the
// shared 4-row z-plane in registers.
// Plane row order: {(0,0),(0,1),(1,0),(1,1)} in (x,y) at fixed z.
__global__ void __launch_bounds__(128, 10) trilerp_main_kernel(
    const float* __restrict__ gv,
    const float* __restrict__ gf,
    float* __restrict__ out_val,   // [B]
    float* __restrict__ out_feat)  // [B, 256]
{
    __shared__ int s_item;
    const int tid  = threadIdx.x;
    const int wid  = tid >> 5;
    const int lane = tid & 31;

    for (;;) {
        if (tid == 0) s_item = atomicAdd(&g_item, 1);
        __syncthreads();
        const int item = s_item;
        __syncthreads();
        if (item >= NITEMS) return;

        const int half   = item >> 12;
        const int region = item & (NREGIONS - 1);
        const int rx0 = ((region >> 8) & 15) << 2;
        const int ry0 = ((region >> 4) & 15) << 2;
        const int rz0 = (region & 15) << 2;

        const int coff = (half << 5) + lane;   // float4 column within 1KB row
        const int keybase = region << 6;

        for (int col = wid; col < 16; col += 4) {
            const int ix = rx0 + (col >> 2);
            const int iy = ry0 + (col & 3);
            const int cigb = col << 2;                     // (lx<<4)|(ly<<2)
            const int rowcol = (ix * N1 + iy) * N1 + rz0;  // z=rz0 row index

            float4 hi0, hi1, hi2, hi3;
            int zhi = -1;

            for (int izl = 0; izl < 4; izl++) {
                const int cstart = g_binstart[keybase + cigb + izl];
                const int cend   = g_binstart[keybase + cigb + izl + 1];
                if (cstart == cend) continue;

                const float4* rp = (const float4*)gf +
                                   (size_t)(rowcol + izl) * (W_FEAT / 4) + coff;

                float4 lo0, lo1, lo2, lo3;
                if (zhi == izl) {
                    lo0 = hi0; lo1 = hi1; lo2 = hi2; lo3 = hi3;
                } else {
                    lo0 = __ldg(rp);                                   // (0,0,z)
                    lo1 = __ldg(rp + N1 * (W_FEAT / 4));               // (0,1,z)
                    lo2 = __ldg(rp + N1 * N1 * (W_FEAT / 4));          // (1,0,z)
                    lo3 = __ldg(rp + (N1 * N1 + N1) * (W_FEAT / 4));   // (1,1,z)
                }
                hi0 = __ldg(rp + (W_FEAT / 4));                        // (0,0,z+1)
                hi1 = __ldg(rp + (N1 + 1) * (W_FEAT / 4));
                hi2 = __ldg(rp + (N1 * N1 + 1) * (W_FEAT / 4));
                hi3 = __ldg(rp + (N1 * N1 + N1 + 1) * (W_FEAT / 4));
                zhi = izl + 1;

                // gv corner value for lanes 0..7 (used by half 0 only).
                float gvrow = 0.0f;
                if (half == 0 && lane < 8) {
                    const int off = ((lane & 4) ? N1 * N1 : 0) +
                                    ((lane & 2) ? N1 : 0) + (lane & 1);
                    gvrow = __ldg(gv + rowcol + izl + off);
                }

                const int izc = rz0 + izl;

                for (int j = cstart; j < cend; j++) {
                    const float4 xp = __ldg(&g_xs[j]);
                    const int p = __float_as_int(xp.w);

                    const float rx = (xp.x + 1.0f) * 32.0f;
                    const float ry = (xp.y + 1.0f) * 32.0f;
                    const float rz = (xp.z + 1.0f) * 32.0f;

                    const bool valid = (rx >= 0.0f) && (rx <= 64.0f) &&
                                       (ry >= 0.0f) && (ry <= 64.0f) &&
                                       (rz >= 0.0f) && (rz <= 64.0f);
                    const float vmask = valid ? 1.0f : 0.0f;

                    const float tx = rx - (float)ix;
                    const float ty = ry - (float)iy;
                    const float tz = rz - (float)izc;
                    const float wx0 = 1.0f - tx, wy0 = 1.0f - ty, wz0 = 1.0f - tz;

                    const float a00 = wx0 * wy0;
                    const float a01 = wx0 * ty;
                    const float a10 = tx  * wy0;
                    const float a11 = tx  * ty;

                    const float wl0 = a00 * wz0, wh0 = a00 * tz;
                    const float wl1 = a01 * wz0, wh1 = a01 * tz;
                    const float wl2 = a10 * wz0, wh2 = a10 * tz;
                    const float wl3 = a11 * wz0, wh3 = a11 * tz;

                    float s0, s1, s2, s3;
                    s0 = wl0 * lo0.x; s1 = wl0 * lo0.y; s2 = wl0 * lo0.z; s3 = wl0 * lo0.w;
                    s0 = fmaf(wl1, lo1.x, s0); s1 = fmaf(wl1, lo1.y, s1);
                    s2 = fmaf(wl1, lo1.z, s2); s3 = fmaf(wl1, lo1.w, s3);
                    s0 = fmaf(wl2, lo2.x, s0); s1 = fmaf(wl2, lo2.y, s1);
                    s2 = fmaf(wl2, lo2.z, s2); s3 = fmaf(wl2, lo2.w, s3);
                    s0 = fmaf(wl3, lo3.x, s0); s1 = fmaf(wl3, lo3.y, s1);
                    s2 = fmaf(wl3, lo3.z, s2); s3 = fmaf(wl3, lo3.w, s3);
                    s0 = fmaf(wh0, hi0.x, s0); s1 = fmaf(wh0, hi0.y, s1);
                    s2 = fmaf(wh0, hi0.z, s2); s3 = fmaf(wh0, hi0.w, s3);
                    s0 = fmaf(wh1, hi1.x, s0); s1 = fmaf(wh1, hi1.y, s1);
                    s2 = fmaf(wh1, hi1.z, s2); s3 = fmaf(wh1, hi1.w, s3);
                    s0 = fmaf(wh2, hi2.x, s0); s1 = fmaf(wh2, hi2.y, s1);
                    s2 = fmaf(wh2, hi2.z, s2); s3 = fmaf(wh2, hi2.w, s3);
                    s0 = fmaf(wh3, hi3.x, s0); s1 = fmaf(wh3, hi3.y, s1);
                    s2 = fmaf(wh3, hi3.z, s2); s3 = fmaf(wh3, hi3.w, s3);

                    float4* frow = (float4*)(out_feat + (size_t)p * W_FEAT);
                    __stcs(frow + coff,
                           make_float4(s0 * vmask, s1 * vmask, s2 * vmask, s3 * vmask));

                    if (half == 0) {
                        const float wxs = (lane & 4) ? tx : wx0;
                        const float wys = (lane & 2) ? ty : wy0;
                        const float wzs = (lane & 1) ? tz : wz0;
                        float gvv = (lane < 8) ? wxs * wys * wzs * gvrow : 0.0f;
                        gvv += __shfl_xor_sync(0xffffffffu, gvv, 4);
                        gvv += __shfl_xor_sync(0xffffffffu, gvv, 2);
                        gvv += __shfl_xor_sync(0xffffffffu, gvv, 1);
                        if (lane == 0) out_val[p] = gvv * vmask;
                    }
                }
            }
        }
    }
}

// Fallback (B > MAXB): direct global-gather version, unsorted.
__global__ void __launch_bounds__(256) trilerp_kernel(
    const float* __restrict__ x,
    const float* __restrict__ gv,
    const float* __restrict__ gf,
    float* __restrict__ out_val,
    float* __restrict__ out_feat,
    int B)
{
    const int p = (blockIdx.x * blockDim.x + threadIdx.x) >> 5;
    const int lane = threadIdx.x & 31;
    if (p >= B) return;

    const float rx = (__ldg(x + p * 3 + 0) + 1.0f) * 32.0f;
    const float ry = (__ldg(x + p * 3 + 1) + 1.0f) * 32.0f;
    const float rz = (__ldg(x + p * 3 + 2) + 1.0f) * 32.0f;
    const bool valid = (rx >= 0.0f) && (rx <= 64.0f) && (ry >= 0.0f) &&
                       (ry <= 64.0f) && (rz >= 0.0f) && (rz <= 64.0f);
    const float vmask = valid ? 1.0f : 0.0f;
    int ix = (int)floorf(rx); ix = ix < 0 ? 0 : (ix > 63 ? 63 : ix);
    int iy = (int)floorf(ry); iy = iy < 0 ? 0 : (iy > 63 ? 63 : iy);
    int iz = (int)floorf(rz); iz = iz < 0 ? 0 : (iz > 63 ? 63 : iz);
    const float tx = rx - ix, ty = ry - iy, tz = rz - iz;
    const int base = (ix * N1 + iy) * N1 + iz;
    const float wx0 = 1.0f - tx, wy0 = 1.0f - ty, wz0 = 1.0f - tz;
    float w[8] = { wx0*wy0*wz0, wx0*wy0*tz, wx0*ty*wz0, wx0*ty*tz,
                   tx*wy0*wz0,  tx*wy0*tz,  tx*ty*wz0,  tx*ty*tz };
    const int offs[8] = { 0, 1, N1, N1+1, N1*N1, N1*N1+1, N1*N1+N1, N1*N1+N1+1 };

    float gvv = 0.0f;
    if (lane < 8) gvv = w[lane] * __ldg(gv + base + offs[lane]);
    gvv += __shfl_xor_sync(0xffffffffu, gvv, 4);
    gvv += __shfl_xor_sync(0xffffffffu, gvv, 2);
    gvv += __shfl_xor_sync(0xffffffffu, gvv, 1);
    if (lane == 0) out_val[p] = gvv * vmask;

    float a0=0,a1=0,a2=0,a3=0,b0=0,b1=0,b2=0,b3=0;
#pragma unroll
    for (int c = 0; c < 8; c++) {
        const float4* row = (const float4*)(gf + (size_t)(base + offs[c]) * W_FEAT);
        const float4 fa = __ldg(row + lane);
        const float4 fb = __ldg(row + lane + 32);
        const float wc = w[c];
        a0 = fmaf(wc, fa.x, a0); a1 = fmaf(wc, fa.y, a1);
        a2 = fmaf(wc, fa.z, a2); a3 = fmaf(wc, fa.w, a3);
        b0 = fmaf(wc, fb.x, b0); b1 = fmaf(wc, fb.y, b1);
        b2 = fmaf(wc, fb.z, b2); b3 = fmaf(wc, fb.w, b3);
    }
    float4* frow = (float4*)(out_feat + (size_t)p * W_FEAT);
    frow[lane]      = make_float4(a0*vmask, a1*vmask, a2*vmask, a3*vmask);
    frow[lane + 32] = make_float4(b0*vmask, b1*vmask, b2*vmask, b3*vmask);
}

extern "C" void kernel_launch(void* const* d_in, const int* in_sizes, int n_in,
                              void* d_out, int out_size)
{
    const float* x  = (const float*)d_in[0];
    const float* gv = (const float*)d_in[1];
    const float* gf = (const float*)d_in[2];
    float* out = (float*)d_out;

    const int B = in_sizes[0] / 3;
    float* out_val  = out;        // [B]
    float* out_feat = out + B;    // [B, 256]

    if (B <= MAXB) {
        histo_kernel<<<(B + 255) / 256, 256>>>(x, B);
        scan1_kernel<<<SCAN_BLOCKS, 1024>>>();
        scan2_kernel<<<1, SCAN_BLOCKS>>>(B);
        fixup_kernel<<<SCAN_BLOCKS, 1024>>>();
        scatter_kernel<<<(B + 255) / 256, 256>>>(x, B);
        trilerp_main_kernel<<<GRID_MAIN, 128>>>(gv, gf, out_val, out_feat);
    } else {
        const int blocks = (B + 7) / 8;
        trilerp_kernel<<<blocks, 256>>>(x, gv, gf, out_val, out_feat, B);
    }
}